// round 1
// baseline (speedup 1.0000x reference)
#include <cuda_runtime.h>
#include <cuda_bf16.h>
#include <cstdint>
#include <math.h>

// Problem constants
#define BB   64
#define TT   128
#define EE   256
#define HH   256
#define BT   (BB*TT)        // 8192

// ---------------------------------------------------------------------------
// Scratch: input-drive buffer xp[B*T, HH] (8 MB), reused for level 0 then 1.
// ---------------------------------------------------------------------------
__device__ float g_xp[BT * HH];

// ---------------------------------------------------------------------------
// GEMM: out[m, n] = sum_k A[row(m), k] * W[n, k] + bias[n]
//   M = 8192 rows (row(m) = rowidx ? rowidx[m] : m, row stride = astride)
//   N = 256, K = 256. Tile 64x64, K-chunks of 32, 4x4 register micro-tile.
// Used for xp0 (A=emb gathered by tokens) and xp1 (A=d_out h0 part, stride 512).
// ---------------------------------------------------------------------------
__global__ __launch_bounds__(256) void gemm_xp(
    const float* __restrict__ A, const int* __restrict__ rowidx, int astride,
    const float* __restrict__ W, const float* __restrict__ bias)
{
    __shared__ float As[32][68];
    __shared__ float Bs[32][68];

    const int m0  = blockIdx.x * 64;
    const int n0  = blockIdx.y * 64;
    const int tid = threadIdx.x;
    const int lr  = tid >> 3;          // 0..31 (loader row)
    const int lk  = (tid & 7) << 2;    // 0,4,...,28 (loader k within chunk)
    const int ty  = tid >> 4;          // 0..15
    const int tx  = tid & 15;          // 0..15

    float acc[4][4] = {};

    for (int k0 = 0; k0 < 256; k0 += 32) {
        #pragma unroll
        for (int rr = 0; rr < 2; rr++) {
            int m  = m0 + lr + rr * 32;
            int ar = rowidx ? rowidx[m] : m;
            float4 a4 = *(const float4*)(A + (size_t)ar * astride + k0 + lk);
            As[lk + 0][lr + rr * 32] = a4.x;
            As[lk + 1][lr + rr * 32] = a4.y;
            As[lk + 2][lr + rr * 32] = a4.z;
            As[lk + 3][lr + rr * 32] = a4.w;

            int n = n0 + lr + rr * 32;
            float4 b4 = *(const float4*)(W + (size_t)n * 256 + k0 + lk);
            Bs[lk + 0][lr + rr * 32] = b4.x;
            Bs[lk + 1][lr + rr * 32] = b4.y;
            Bs[lk + 2][lr + rr * 32] = b4.z;
            Bs[lk + 3][lr + rr * 32] = b4.w;
        }
        __syncthreads();

        #pragma unroll
        for (int kk = 0; kk < 32; kk++) {
            float a[4], b[4];
            *(float4*)a = *(const float4*)&As[kk][ty << 2];
            *(float4*)b = *(const float4*)&Bs[kk][tx << 2];
            #pragma unroll
            for (int i = 0; i < 4; i++)
                #pragma unroll
                for (int j = 0; j < 4; j++)
                    acc[i][j] = fmaf(a[i], b[j], acc[i][j]);
        }
        __syncthreads();
    }

    // Epilogue: add bias, vectorized store into g_xp
    float4 bv = *(const float4*)(bias + n0 + (tx << 2));
    #pragma unroll
    for (int i = 0; i < 4; i++) {
        int m = m0 + (ty << 2) + i;
        float4 o;
        o.x = acc[i][0] + bv.x;
        o.y = acc[i][1] + bv.y;
        o.z = acc[i][2] + bv.z;
        o.w = acc[i][3] + bv.w;
        *(float4*)(g_xp + (size_t)m * 256 + n0 + (tx << 2)) = o;
    }
}

// ---------------------------------------------------------------------------
// LTC scan kernel: 4-CTA clusters, 32 clusters (128 CTAs).
//   Cluster c handles batch pair (2c, 2c+1). CTA rank r owns neurons
//   [64r, 64r+64). Masked recurrent weights live in SMEM (k-major,
//   stride 72 floats => conflict-free reads for the (jl, ks) lane layout).
//   Hidden state h (both batch elems packed as float2) is replicated in every
//   CTA's SMEM, double-buffered; each step every CTA broadcasts its 64-neuron
//   slice to all 4 CTAs via st.shared::cluster, then barrier.cluster.
// ---------------------------------------------------------------------------
#define CS  4      // cluster size
#define JP  64     // neurons per CTA
#define WS  72     // Wsh row stride in floats (72 % 32 == 8 -> bank-disjoint)
#define SCAN_SMEM (HH*WS*4 + 2*HH*8)   // 73728 + 4096 = 77824 bytes

__device__ __forceinline__ uint32_t smem_u32(const void* p) {
    return (uint32_t)__cvta_generic_to_shared(p);
}

__global__ void __cluster_dims__(CS, 1, 1) __launch_bounds__(256, 1)
ltc_scan(const float* __restrict__ Wrec, const float* __restrict__ mask,
         const float* __restrict__ tau_raw, float* __restrict__ out,
         int outoff)
{
    extern __shared__ float smem[];
    float*  Wsh = smem;                             // [256][WS]
    float2* hb0 = (float2*)(smem + HH * WS);        // [256] pairs
    float2* hb1 = hb0 + HH;                         // [256] pairs

    uint32_t rank;
    asm("mov.u32 %0, %%cluster_ctarank;" : "=r"(rank));
    const int cl    = blockIdx.x / CS;
    const int b0    = cl * 2;
    const int b1    = b0 + 1;
    const int jbase = (int)rank * JP;

    const int tid  = threadIdx.x;
    const int lane = tid & 31;
    const int warp = tid >> 5;
    const int jl   = lane & 7;     // neuron-within-warp
    const int ks   = lane >> 3;    // k-slice 0..3
    const int j    = warp * 8 + jl;        // local neuron 0..63
    const int jf   = jbase + j;            // global neuron 0..255

    // Load masked recurrent weight slice, transposed to k-major in SMEM.
    for (int e = tid; e < JP * HH; e += 256) {
        int jj = e >> 8;       // 0..63
        int kk = e & 255;
        int g  = (jbase + jj) * HH + kk;
        Wsh[kk * WS + jj] = Wrec[g] * mask[g];
    }
    // Zero both h buffers (own CTA's copies).
    if (tid < HH) {
        hb0[tid] = make_float2(0.f, 0.f);
        hb1[tid] = make_float2(0.f, 0.f);
    }

    // Per-thread inverse time constant for its neuron.
    const float tr     = tau_raw[jf];
    const float invtau = 1.0f / (log1pf(expf(tr)) + 0.1f);

    __syncthreads();
    asm volatile("barrier.cluster.arrive.aligned;" ::: "memory");
    asm volatile("barrier.cluster.wait.aligned;"   ::: "memory");

    for (int t = 0; t < TT; t++) {
        const float2* hr = (t & 1) ? hb1 : hb0;   // h_{t-1}
        float2*       hw = (t & 1) ? hb0 : hb1;   // h_t (to be written)

        // Prefetch input drive early (consumed after the GEMV).
        float xq0 = 0.f, xq1 = 0.f;
        if (ks == 0) {
            xq0 = g_xp[(size_t)(b0 * TT + t) * HH + jf];
            xq1 = g_xp[(size_t)(b1 * TT + t) * HH + jf];
        }

        // GEMV slice: pre[b][j] partial over k = ks + 4i
        float a0 = 0.f, a1 = 0.f;
        #pragma unroll 8
        for (int i = 0; i < 64; i++) {
            int k    = ks + (i << 2);
            float w  = Wsh[k * WS + j];
            float2 h = hr[k];
            a0 = fmaf(w, h.x, a0);
            a1 = fmaf(w, h.y, a1);
        }
        // Reduce across the 4 k-slices (lanes differing in bits 3,4).
        a0 += __shfl_xor_sync(0xffffffffu, a0, 8);
        a0 += __shfl_xor_sync(0xffffffffu, a0, 16);
        a1 += __shfl_xor_sync(0xffffffffu, a1, 8);
        a1 += __shfl_xor_sync(0xffffffffu, a1, 16);

        if (ks == 0) {
            float2 hold = hr[jf];
            float hn0 = hold.x + (tanhf(a0 + xq0) - hold.x) * invtau;
            float hn1 = hold.y + (tanhf(a1 + xq1) - hold.y) * invtau;

            out[(size_t)(b0 * TT + t) * 512 + outoff + jf] = hn0;
            out[(size_t)(b1 * TT + t) * 512 + outoff + jf] = hn1;

            float2 v = make_float2(hn0, hn1);
            unsigned long long vv;
            __builtin_memcpy(&vv, &v, 8);
            uint32_t la = smem_u32(&hw[jf]);
            #pragma unroll
            for (int c = 0; c < CS; c++) {
                asm volatile(
                    "{ .reg .u32 ra;\n\t"
                    "  mapa.shared::cluster.u32 ra, %0, %1;\n\t"
                    "  st.shared::cluster.b64 [ra], %2; }"
                    :: "r"(la), "r"(c), "l"(vv) : "memory");
            }
        }

        // Release the remote stores / acquire peers' slices.
        asm volatile("barrier.cluster.arrive.aligned;" ::: "memory");
        asm volatile("barrier.cluster.wait.aligned;"   ::: "memory");
    }
}

// ---------------------------------------------------------------------------
// Launch: gemm(xp0) -> scan0 -> gemm(xp1 from h0 in d_out) -> scan1
// ---------------------------------------------------------------------------
extern "C" void kernel_launch(void* const* d_in, const int* in_sizes, int n_in,
                              void* d_out, int out_size)
{
    const int*   tokens = (const int*)  d_in[0];
    const float* emb    = (const float*)d_in[1];
    const float* W_in0  = (const float*)d_in[2];
    const float* W_rec0 = (const float*)d_in[3];
    const float* b0     = (const float*)d_in[4];
    const float* tau0   = (const float*)d_in[5];
    const float* mask0  = (const float*)d_in[6];
    const float* W_in1  = (const float*)d_in[7];
    const float* W_rec1 = (const float*)d_in[8];
    const float* b1     = (const float*)d_in[9];
    const float* tau1   = (const float*)d_in[10];
    const float* mask1  = (const float*)d_in[11];
    float* out = (float*)d_out;

    (void)in_sizes; (void)n_in; (void)out_size;

    cudaFuncSetAttribute(ltc_scan,
                         cudaFuncAttributeMaxDynamicSharedMemorySize,
                         SCAN_SMEM);

    dim3 ggrid(BT / 64, HH / 64);   // 128 x 4

    // Level 0 input drive: gather emb rows by token id.
    gemm_xp<<<ggrid, 256>>>(emb, tokens, EE, W_in0, b0);
    // Level 0 scan -> out[..., 0:256]
    ltc_scan<<<128, 256, SCAN_SMEM>>>(W_rec0, mask0, tau0, out, 0);
    // Level 1 input drive: read h0_seq straight out of d_out (stride 512).
    gemm_xp<<<ggrid, 256>>>(out, nullptr, 512, W_in1, b1);
    // Level 1 scan -> out[..., 256:512]
    ltc_scan<<<128, 256, SCAN_SMEM>>>(W_rec1, mask1, tau1, out, 256);
}

// round 2
// speedup vs baseline: 1.7351x; 1.7351x over previous
#include <cuda_runtime.h>
#include <cuda_bf16.h>
#include <cstdint>
#include <math.h>

// Problem constants
#define BB   64
#define TT   128
#define EE   256
#define HH   256
#define BT   (BB*TT)        // 8192

// Scratch: input-drive buffer xp[B*T, HH] (8 MB), reused for level 0 then 1.
__device__ float g_xp[BT * HH];

// ---------------------------------------------------------------------------
// GEMM: g_xp[m, n] = sum_k A[row(m), k] * W[n, k] + bias[n]
// ---------------------------------------------------------------------------
__global__ __launch_bounds__(256) void gemm_xp(
    const float* __restrict__ A, const int* __restrict__ rowidx, int astride,
    const float* __restrict__ W, const float* __restrict__ bias)
{
    __shared__ float As[32][68];
    __shared__ float Bs[32][68];

    const int m0  = blockIdx.x * 64;
    const int n0  = blockIdx.y * 64;
    const int tid = threadIdx.x;
    const int lr  = tid >> 3;
    const int lk  = (tid & 7) << 2;
    const int ty  = tid >> 4;
    const int tx  = tid & 15;

    float acc[4][4] = {};

    for (int k0 = 0; k0 < 256; k0 += 32) {
        #pragma unroll
        for (int rr = 0; rr < 2; rr++) {
            int m  = m0 + lr + rr * 32;
            int ar = rowidx ? rowidx[m] : m;
            float4 a4 = *(const float4*)(A + (size_t)ar * astride + k0 + lk);
            As[lk + 0][lr + rr * 32] = a4.x;
            As[lk + 1][lr + rr * 32] = a4.y;
            As[lk + 2][lr + rr * 32] = a4.z;
            As[lk + 3][lr + rr * 32] = a4.w;

            int n = n0 + lr + rr * 32;
            float4 b4 = *(const float4*)(W + (size_t)n * 256 + k0 + lk);
            Bs[lk + 0][lr + rr * 32] = b4.x;
            Bs[lk + 1][lr + rr * 32] = b4.y;
            Bs[lk + 2][lr + rr * 32] = b4.z;
            Bs[lk + 3][lr + rr * 32] = b4.w;
        }
        __syncthreads();

        #pragma unroll
        for (int kk = 0; kk < 32; kk++) {
            float a[4], b[4];
            *(float4*)a = *(const float4*)&As[kk][ty << 2];
            *(float4*)b = *(const float4*)&Bs[kk][tx << 2];
            #pragma unroll
            for (int i = 0; i < 4; i++)
                #pragma unroll
                for (int j = 0; j < 4; j++)
                    acc[i][j] = fmaf(a[i], b[j], acc[i][j]);
        }
        __syncthreads();
    }

    float4 bv = *(const float4*)(bias + n0 + (tx << 2));
    #pragma unroll
    for (int i = 0; i < 4; i++) {
        int m = m0 + (ty << 2) + i;
        float4 o;
        o.x = acc[i][0] + bv.x;
        o.y = acc[i][1] + bv.y;
        o.z = acc[i][2] + bv.z;
        o.w = acc[i][3] + bv.w;
        *(float4*)(g_xp + (size_t)m * 256 + n0 + (tx << 2)) = o;
    }
}

// ---------------------------------------------------------------------------
// LTC scan: 4-CTA clusters, 32 clusters (128 CTAs), 2 batch elems / cluster.
//   - Masked recurrent weights held entirely in REGISTERS (64 f32/thread,
//     packed as 32 f32x2 pairs along k).
//   - GEMV uses fma.rn.f32x2; h is read from SMEM as ulonglong2 (LDS.128,
//     broadcast across the 8 same-ks lanes; ks segments padded by 4 floats
//     so the 4 ks groups hit disjoint bank groups).
//   - Cross-CTA h exchange: st.async.shared::cluster with
//     mbarrier::complete_tx (2048 B expected per CTA per step). Triple
//     buffering makes the <=1-step skew safe without a full cluster barrier.
// ---------------------------------------------------------------------------
#define CS  4
#define JP  64
#define SEG 68          // per-ks segment stride (floats): 64 data + 4 pad

typedef unsigned long long u64t;

__device__ __forceinline__ uint32_t smem_u32(const void* p) {
    return (uint32_t)__cvta_generic_to_shared(p);
}
__device__ __forceinline__ u64t pk2(float x, float y) {
    u64t r; asm("mov.b64 %0, {%1,%2};" : "=l"(r) : "f"(x), "f"(y)); return r;
}
__device__ __forceinline__ void fma2(u64t& d, u64t a, u64t b) {
    asm("fma.rn.f32x2 %0, %1, %2, %0;" : "+l"(d) : "l"(a), "l"(b));
}
__device__ __forceinline__ float hsum2(u64t v) {
    float a, b; asm("mov.b64 {%0,%1}, %2;" : "=f"(a), "=f"(b) : "l"(v));
    return a + b;
}

__global__ void __cluster_dims__(CS, 1, 1) __launch_bounds__(256, 1)
ltc_scan(const float* __restrict__ Wrec, const float* __restrict__ mask,
         const float* __restrict__ tau_raw, float* __restrict__ out,
         int outoff)
{
    // 3 time-buffers x 2 batch x 272 floats = 6528 B, + mbarrier
    __shared__ __align__(16) float hb[3][2][4 * SEG];
    __shared__ u64t mbar;

    uint32_t rank;
    asm("mov.u32 %0, %%cluster_ctarank;" : "=r"(rank));
    const int cl    = blockIdx.x / CS;
    const int b0    = cl * 2;
    const int b1    = b0 + 1;
    const int jbase = (int)rank * JP;

    const int tid  = threadIdx.x;
    const int lane = tid & 31;
    const int warp = tid >> 5;
    const int jl   = lane & 7;      // neuron within warp
    const int ks   = lane >> 3;     // k-slice 0..3
    const int j    = warp * 8 + jl; // local neuron 0..63
    const int jf   = jbase + j;     // global neuron 0..255
    const int kbase = ks * 64;

    const uint32_t mbar_sa = smem_u32(&mbar);
    if (tid == 0)
        asm volatile("mbarrier.init.shared.b64 [%0], 1;" :: "r"(mbar_sa) : "memory");

    // Zero all h buffers.
    for (int e = tid; e < 3 * 2 * 4 * SEG; e += 256)
        ((float*)hb)[e] = 0.f;

    // Load this thread's 64 masked weights into registers (32 f32x2 pairs).
    u64t w2[32];
    {
        const float4* wr = (const float4*)(Wrec + (size_t)jf * HH + kbase);
        const float4* mr = (const float4*)(mask + (size_t)jf * HH + kbase);
        #pragma unroll
        for (int ii = 0; ii < 16; ii++) {
            float4 wv = __ldg(wr + ii);
            float4 mv = __ldg(mr + ii);
            w2[2 * ii + 0] = pk2(wv.x * mv.x, wv.y * mv.y);
            w2[2 * ii + 1] = pk2(wv.z * mv.z, wv.w * mv.w);
        }
    }

    const float tr     = tau_raw[jf];
    const float invtau = 1.0f / (log1pf(expf(tr)) + 0.1f);

    const bool prod = (ks == 0);
    const int  widx = jf + ((jf >> 6) << 2);   // padded slot for neuron jf

    __syncthreads();
    asm volatile("barrier.cluster.arrive.aligned;" ::: "memory");
    asm volatile("barrier.cluster.wait.aligned;"   ::: "memory");

    int wb = 0, rb = 2;   // write buffer (step t), read buffer (step t-1)

    for (int t = 0; t < TT; t++) {
        // Arm this step's tx expectation (1 arrival + 2048 bytes).
        if (tid == 0)
            asm volatile("mbarrier.arrive.expect_tx.shared.b64 _, [%0], 2048;"
                         :: "r"(mbar_sa) : "memory");

        // Prefetch input drive (consumed after the GEMV).
        float xq0 = 0.f, xq1 = 0.f;
        if (prod) {
            xq0 = __ldg(g_xp + (size_t)(b0 * TT + t) * HH + jf);
            xq1 = __ldg(g_xp + (size_t)(b1 * TT + t) * HH + jf);
        }

        // GEMV slice over k in [kbase, kbase+64)
        const ulonglong2* p0 = (const ulonglong2*)(&hb[rb][0][ks * SEG]);
        const ulonglong2* p1 = (const ulonglong2*)(&hb[rb][1][ks * SEG]);
        u64t a0a = 0, a0b = 0, a1a = 0, a1b = 0;
        #pragma unroll
        for (int ii = 0; ii < 16; ii++) {
            ulonglong2 v0 = p0[ii];
            ulonglong2 v1 = p1[ii];
            fma2(a0a, w2[2 * ii + 0], v0.x);
            fma2(a0b, w2[2 * ii + 1], v0.y);
            fma2(a1a, w2[2 * ii + 0], v1.x);
            fma2(a1b, w2[2 * ii + 1], v1.y);
        }
        float s0 = hsum2(a0a) + hsum2(a0b);
        float s1 = hsum2(a1a) + hsum2(a1b);
        // Reduce across the 4 k-slices (lanes differing in bits 3,4).
        s0 += __shfl_xor_sync(0xffffffffu, s0, 8);
        s0 += __shfl_xor_sync(0xffffffffu, s0, 16);
        s1 += __shfl_xor_sync(0xffffffffu, s1, 8);
        s1 += __shfl_xor_sync(0xffffffffu, s1, 16);

        if (prod) {
            float h0old = hb[rb][0][widx];
            float h1old = hb[rb][1][widx];
            float hn0 = h0old + (tanhf(s0 + xq0) - h0old) * invtau;
            float hn1 = h1old + (tanhf(s1 + xq1) - h1old) * invtau;

            out[(size_t)(b0 * TT + t) * 512 + outoff + jf] = hn0;
            out[(size_t)(b1 * TT + t) * 512 + outoff + jf] = hn1;

            uint32_t la0 = smem_u32(&hb[wb][0][widx]);
            uint32_t la1 = smem_u32(&hb[wb][1][widx]);
            #pragma unroll
            for (int c = 0; c < CS; c++) {
                asm volatile(
                    "{ .reg .u32 ra, rb2, rm;\n\t"
                    "  mapa.shared::cluster.u32 ra,  %0, %3;\n\t"
                    "  mapa.shared::cluster.u32 rb2, %1, %3;\n\t"
                    "  mapa.shared::cluster.u32 rm,  %2, %3;\n\t"
                    "  st.async.shared::cluster.mbarrier::complete_tx::bytes.b32 [ra],  %4, [rm];\n\t"
                    "  st.async.shared::cluster.mbarrier::complete_tx::bytes.b32 [rb2], %5, [rm]; }"
                    :: "r"(la0), "r"(la1), "r"(mbar_sa), "r"(c),
                       "f"(hn0), "f"(hn1) : "memory");
            }
        }

        // Wait for all 2048 bytes (256 neurons x 2 batch) of step t to land.
        {
            const uint32_t par = (uint32_t)(t & 1);
            asm volatile(
                "{ .reg .pred p;\n\t"
                "WAIT_%=:\n\t"
                "  mbarrier.try_wait.parity.acquire.cluster.shared::cta.b64 p, [%0], %1, 0x989680;\n\t"
                "  @!p bra WAIT_%=;\n\t"
                "}"
                :: "r"(mbar_sa), "r"(par) : "memory");
        }

        rb = wb;
        wb = (wb == 2) ? 0 : wb + 1;
    }
}

// ---------------------------------------------------------------------------
// Launch: gemm(xp0) -> scan0 -> gemm(xp1 from h0 in d_out) -> scan1
// ---------------------------------------------------------------------------
extern "C" void kernel_launch(void* const* d_in, const int* in_sizes, int n_in,
                              void* d_out, int out_size)
{
    const int*   tokens = (const int*)  d_in[0];
    const float* emb    = (const float*)d_in[1];
    const float* W_in0  = (const float*)d_in[2];
    const float* W_rec0 = (const float*)d_in[3];
    const float* b0     = (const float*)d_in[4];
    const float* tau0   = (const float*)d_in[5];
    const float* mask0  = (const float*)d_in[6];
    const float* W_in1  = (const float*)d_in[7];
    const float* W_rec1 = (const float*)d_in[8];
    const float* b1     = (const float*)d_in[9];
    const float* tau1   = (const float*)d_in[10];
    const float* mask1  = (const float*)d_in[11];
    float* out = (float*)d_out;

    (void)in_sizes; (void)n_in; (void)out_size;

    dim3 ggrid(BT / 64, HH / 64);   // 128 x 4

    gemm_xp<<<ggrid, 256>>>(emb, tokens, EE, W_in0, b0);
    ltc_scan<<<128, 256>>>(W_rec0, mask0, tau0, out, 0);
    gemm_xp<<<ggrid, 256>>>(out, nullptr, 512, W_in1, b1);
    ltc_scan<<<128, 256>>>(W_rec1, mask1, tau1, out, 256);
}